// round 2
// baseline (speedup 1.0000x reference)
#include <cuda_runtime.h>
#include <cstddef>

#define DIM 128
#define N_ITEMS 100000
#define N_BASKETS 50000
#define NUM_LAYER 3

// Static device scratch (no cudaMalloc anywhere).
// Per-layer results kept separate so running sums fold into finalize.
__device__ float g_basket[NUM_LAYER][(size_t)N_BASKETS * DIM];  // 3 x 25.6 MB
__device__ float g_cur[NUM_LAYER][(size_t)N_ITEMS * DIM];       // 3 x 51.2 MB

// Zero all scratch buffers in one launch (grid-stride float4 stores).
__global__ void zero_scratch() {
    const size_t nb4 = (size_t)NUM_LAYER * N_BASKETS * DIM / 4;
    const size_t ni4 = (size_t)NUM_LAYER * N_ITEMS * DIM / 4;
    float4* b = reinterpret_cast<float4*>(&g_basket[0][0]);
    float4* c = reinterpret_cast<float4*>(&g_cur[0][0]);
    const float4 z = {0.f, 0.f, 0.f, 0.f};
    size_t stride = (size_t)gridDim.x * blockDim.x;
    for (size_t i = blockIdx.x * (size_t)blockDim.x + threadIdx.x; i < nb4; i += stride)
        b[i] = z;
    for (size_t i = blockIdx.x * (size_t)blockDim.x + threadIdx.x; i < ni4; i += stride)
        c[i] = z;
}

// Warp-per-edge COO scatter core: dst[rows[e], :] += vals[e] * src[cols[e], :]
__device__ __forceinline__ void spmm_edge(const int* __restrict__ rows,
                                          const int* __restrict__ cols,
                                          const float* __restrict__ vals,
                                          const float* __restrict__ src,
                                          float* __restrict__ dst,
                                          int nnz) {
    int warp = (int)((blockIdx.x * (unsigned)blockDim.x + threadIdx.x) >> 5);
    int lane = threadIdx.x & 31;
    if (warp >= nnz) return;

    int r = __ldg(rows + warp);
    int c = __ldg(cols + warp);
    float v = __ldg(vals + warp);

    const float4* s = reinterpret_cast<const float4*>(src + (size_t)c * DIM);
    float4 a = __ldg(s + lane);
    a.x *= v; a.y *= v; a.z *= v; a.w *= v;

    float* d = dst + (size_t)r * DIM + (size_t)lane * 4;
    asm volatile("red.global.add.v4.f32 [%0], {%1, %2, %3, %4};"
                 :: "l"(d), "f"(a.x), "f"(a.y), "f"(a.z), "f"(a.w)
                 : "memory");
}

// basket[layer] = B @ (layer==0 ? x : cur[layer-1])
__global__ void spmm_b(const int* __restrict__ rows,
                       const int* __restrict__ cols,
                       const float* __restrict__ vals,
                       const float* __restrict__ x,
                       int layer, int nnz) {
    const float* src = (layer == 0) ? x : &g_cur[layer - 1][0];
    spmm_edge(rows, cols, vals, src, &g_basket[layer][0], nnz);
}

// cur[layer] = I @ basket[layer]
__global__ void spmm_i(const int* __restrict__ rows,
                       const int* __restrict__ cols,
                       const float* __restrict__ vals,
                       int layer, int nnz) {
    spmm_edge(rows, cols, vals, &g_basket[layer][0], &g_cur[layer][0], nnz);
}

// out[0 : n_item4)          = (x + c0 + c1 + c2) / 4
// out[n_item4 : +n_basket4) = (b0 + b1 + b2) / 3
__global__ void finalize(const float4* __restrict__ x,
                         float4* __restrict__ out,
                         int n_item4, int n_basket4) {
    int i = blockIdx.x * blockDim.x + threadIdx.x;
    if (i < n_item4) {
        const float4* c0 = reinterpret_cast<const float4*>(&g_cur[0][0]);
        const float4* c1 = reinterpret_cast<const float4*>(&g_cur[1][0]);
        const float4* c2 = reinterpret_cast<const float4*>(&g_cur[2][0]);
        float4 a = x[i], p = c0[i], q = c1[i], r = c2[i];
        float4 o;
        o.x = (a.x + p.x + q.x + r.x) * 0.25f;
        o.y = (a.y + p.y + q.y + r.y) * 0.25f;
        o.z = (a.z + p.z + q.z + r.z) * 0.25f;
        o.w = (a.w + p.w + q.w + r.w) * 0.25f;
        out[i] = o;
    } else if (i < n_item4 + n_basket4) {
        int j = i - n_item4;
        const float4* b0 = reinterpret_cast<const float4*>(&g_basket[0][0]);
        const float4* b1 = reinterpret_cast<const float4*>(&g_basket[1][0]);
        const float4* b2 = reinterpret_cast<const float4*>(&g_basket[2][0]);
        float4 p = b0[j], q = b1[j], r = b2[j];
        const float s = 1.0f / 3.0f;
        float4 o;
        o.x = (p.x + q.x + r.x) * s;
        o.y = (p.y + q.y + r.y) * s;
        o.z = (p.z + q.z + r.z) * s;
        o.w = (p.w + q.w + r.w) * s;
        out[i] = o;
    }
}

extern "C" void kernel_launch(void* const* d_in, const int* in_sizes, int n_in,
                              void* d_out, int out_size) {
    const float* x      = (const float*)d_in[0];
    const int*   b_rows = (const int*)  d_in[1];
    const int*   b_cols = (const int*)  d_in[2];
    const float* b_vals = (const float*)d_in[3];
    const int*   i_rows = (const int*)  d_in[4];
    const int*   i_cols = (const int*)  d_in[5];
    const float* i_vals = (const float*)d_in[6];
    float* out = (float*)d_out;

    const int nnz_b = in_sizes[1];
    const int nnz_i = in_sizes[4];

    const int n_basket4 = N_BASKETS * DIM / 4;  // 1,600,000
    const int n_item4   = N_ITEMS * DIM / 4;    // 3,200,000

    const int T = 256;
    const int spmm_blocks_b = (nnz_b + (T / 32) - 1) / (T / 32);
    const int spmm_blocks_i = (nnz_i + (T / 32) - 1) / (T / 32);

    // Zero all per-layer scratch in one launch.
    zero_scratch<<<148 * 8, T>>>();

    for (int layer = 0; layer < NUM_LAYER; layer++) {
        spmm_b<<<spmm_blocks_b, T>>>(b_rows, b_cols, b_vals, x, layer, nnz_b);
        spmm_i<<<spmm_blocks_i, T>>>(i_rows, i_cols, i_vals, layer, nnz_i);
    }

    const int n_tot4 = n_item4 + n_basket4;
    finalize<<<(n_tot4 + T - 1) / T, T>>>((const float4*)x, (float4*)out,
                                          n_item4, n_basket4);
}

// round 3
// speedup vs baseline: 1.4067x; 1.4067x over previous
#include <cuda_runtime.h>
#include <cstddef>

#define DIM 128
#define N_ITEMS 100000
#define N_BASKETS 50000
#define NUM_LAYER 3
#define NNZ_MAX 1000000

typedef unsigned long long u64;

// ---------------- static device scratch (no cudaMalloc anywhere) -------------
__device__ float g_basket[NUM_LAYER][(size_t)N_BASKETS * DIM];  // 3 x 25.6 MB
__device__ float g_cur[NUM_LAYER][(size_t)N_ITEMS * DIM];       // 3 x 51.2 MB

// CSR for B (baskets x items) and I (items x baskets)
__device__ u64 g_edges_b[NNZ_MAX];          // packed (col | val<<32)
__device__ u64 g_edges_i[NNZ_MAX];
__device__ int g_rp_b[N_BASKETS + 1];       // row pointers
__device__ int g_rp_i[N_ITEMS + 1];
__device__ int g_cnt_b[N_BASKETS];          // histogram counters
__device__ int g_cnt_i[N_ITEMS];
__device__ int g_cur_b[N_BASKETS];          // scatter cursors
__device__ int g_cur_i[N_ITEMS];

// ---------------- CSR build --------------------------------------------------

__global__ void zero_counters() {
    int stride = gridDim.x * blockDim.x;
    for (int i = blockIdx.x * blockDim.x + threadIdx.x; i < N_BASKETS; i += stride)
        g_cnt_b[i] = 0;
    for (int i = blockIdx.x * blockDim.x + threadIdx.x; i < N_ITEMS; i += stride)
        g_cnt_i[i] = 0;
}

__global__ void histogram(const int* __restrict__ rows, int* __restrict__ cnt, int nnz) {
    int stride = gridDim.x * blockDim.x;
    for (int e = blockIdx.x * blockDim.x + threadIdx.x; e < nnz; e += stride)
        atomicAdd(&cnt[__ldg(rows + e)], 1);
}

// Single-block exclusive scan: rp[i] = prefix, cursor[i] = prefix, rp[n] = total.
__global__ void scan_rows(const int* __restrict__ cnt, int* __restrict__ rp,
                          int* __restrict__ cursor, int n) {
    __shared__ int sums[1024];
    int t = threadIdx.x;
    int C = (n + 1023) / 1024;
    int lo = t * C, hi = min(lo + C, n);
    int s = 0;
    for (int i = lo; i < hi; i++) s += cnt[i];
    sums[t] = s;
    __syncthreads();
    // Hillis-Steele inclusive scan over 1024 partials
    for (int off = 1; off < 1024; off <<= 1) {
        int v = (t >= off) ? sums[t - off] : 0;
        __syncthreads();
        sums[t] += v;
        __syncthreads();
    }
    int prefix = (t == 0) ? 0 : sums[t - 1];
    for (int i = lo; i < hi; i++) {
        int c = cnt[i];
        rp[i] = prefix;
        cursor[i] = prefix;
        prefix += c;
    }
    if (t == 1023) rp[n] = sums[1023];
}

__global__ void scatter_edges(const int* __restrict__ rows,
                              const int* __restrict__ cols,
                              const float* __restrict__ vals,
                              int* __restrict__ cursor,
                              u64* __restrict__ edges, int nnz) {
    int stride = gridDim.x * blockDim.x;
    for (int e = blockIdx.x * blockDim.x + threadIdx.x; e < nnz; e += stride) {
        int r = __ldg(rows + e);
        int c = __ldg(cols + e);
        unsigned v = __float_as_uint(__ldg(vals + e));
        int pos = atomicAdd(&cursor[r], 1);
        edges[pos] = (u64)(unsigned)c | ((u64)v << 32);
    }
}

// ---------------- CSR SpMM: warp per row, register accumulation --------------
__global__ void spmm_csr(const u64* __restrict__ edges,
                         const int* __restrict__ rp,
                         const float* __restrict__ src,
                         float* __restrict__ dst, int nrows) {
    int row = (int)((blockIdx.x * (unsigned)blockDim.x + threadIdx.x) >> 5);
    int lane = threadIdx.x & 31;
    if (row >= nrows) return;

    int s = __ldg(rp + row);
    int e = __ldg(rp + row + 1);

    float4 acc = {0.f, 0.f, 0.f, 0.f};
    for (int base = s; base < e; base += 32) {
        int m = min(32, e - base);
        u64 p = (lane < m) ? __ldg(edges + base + lane) : 0ULL;
        #pragma unroll 4
        for (int k = 0; k < m; k++) {
            u64 pk = __shfl_sync(0xffffffffu, p, k);
            int col = (int)(unsigned)(pk & 0xffffffffu);
            float val = __uint_as_float((unsigned)(pk >> 32));
            float4 sv = __ldg(reinterpret_cast<const float4*>(src + (size_t)col * DIM) + lane);
            acc.x += val * sv.x;
            acc.y += val * sv.y;
            acc.z += val * sv.z;
            acc.w += val * sv.w;
        }
    }
    reinterpret_cast<float4*>(dst + (size_t)row * DIM)[lane] = acc;
}

// ---------------- finalize ---------------------------------------------------
// out[0 : n_item4)          = (x + c0 + c1 + c2) / 4
// out[n_item4 : +n_basket4) = (b0 + b1 + b2) / 3
__global__ void finalize(const float4* __restrict__ x,
                         float4* __restrict__ out,
                         int n_item4, int n_basket4) {
    int i = blockIdx.x * blockDim.x + threadIdx.x;
    if (i < n_item4) {
        const float4* c0 = reinterpret_cast<const float4*>(&g_cur[0][0]);
        const float4* c1 = reinterpret_cast<const float4*>(&g_cur[1][0]);
        const float4* c2 = reinterpret_cast<const float4*>(&g_cur[2][0]);
        float4 a = x[i], p = c0[i], q = c1[i], r = c2[i];
        float4 o;
        o.x = (a.x + p.x + q.x + r.x) * 0.25f;
        o.y = (a.y + p.y + q.y + r.y) * 0.25f;
        o.z = (a.z + p.z + q.z + r.z) * 0.25f;
        o.w = (a.w + p.w + q.w + r.w) * 0.25f;
        out[i] = o;
    } else if (i < n_item4 + n_basket4) {
        int j = i - n_item4;
        const float4* b0 = reinterpret_cast<const float4*>(&g_basket[0][0]);
        const float4* b1 = reinterpret_cast<const float4*>(&g_basket[1][0]);
        const float4* b2 = reinterpret_cast<const float4*>(&g_basket[2][0]);
        float4 p = b0[j], q = b1[j], r = b2[j];
        const float s = 1.0f / 3.0f;
        float4 o;
        o.x = (p.x + q.x + r.x) * s;
        o.y = (p.y + q.y + r.y) * s;
        o.z = (p.z + q.z + r.z) * s;
        o.w = (p.w + q.w + r.w) * s;
        out[i] = o;
    }
}

// -------- device-pointer trampolines (avoid host cudaGetSymbolAddress) -------
__global__ void spmm_b_layer(const float* __restrict__ x, int layer, int) {}

extern "C" void kernel_launch(void* const* d_in, const int* in_sizes, int n_in,
                              void* d_out, int out_size) {
    const float* x      = (const float*)d_in[0];
    const int*   b_rows = (const int*)  d_in[1];
    const int*   b_cols = (const int*)  d_in[2];
    const float* b_vals = (const float*)d_in[3];
    const int*   i_rows = (const int*)  d_in[4];
    const int*   i_cols = (const int*)  d_in[5];
    const float* i_vals = (const float*)d_in[6];
    float* out = (float*)d_out;

    const int nnz_b = in_sizes[1];
    const int nnz_i = in_sizes[4];

    // Resolve device-symbol addresses once per call (host API, not captured work;
    // returns immediately, safe under graph capture).
    static void *pb = nullptr, *pc = nullptr, *peb = nullptr, *pei = nullptr,
                *prb = nullptr, *pri = nullptr, *pcb = nullptr, *pci = nullptr;
    if (!pb) {
        cudaGetSymbolAddress(&pb, g_basket);
        cudaGetSymbolAddress(&pc, g_cur);
        cudaGetSymbolAddress(&peb, g_edges_b);
        cudaGetSymbolAddress(&pei, g_edges_i);
        cudaGetSymbolAddress(&prb, g_rp_b);
        cudaGetSymbolAddress(&pri, g_rp_i);
        cudaGetSymbolAddress(&pcb, g_cur_b);
        cudaGetSymbolAddress(&pci, g_cur_i);
    }
    float* basket = (float*)pb;   // [layer][N_BASKETS*DIM]
    float* curbuf = (float*)pc;   // [layer][N_ITEMS*DIM]
    u64* edges_b = (u64*)peb;
    u64* edges_i = (u64*)pei;
    int* rp_b = (int*)prb;
    int* rp_i = (int*)pri;
    int* cur_b = (int*)pcb;
    int* cur_i = (int*)pci;

    void *pcnb, *pcni;
    cudaGetSymbolAddress(&pcnb, g_cnt_b);
    cudaGetSymbolAddress(&pcni, g_cnt_i);
    int* cnt_b = (int*)pcnb;
    int* cnt_i = (int*)pcni;

    const int T = 256;
    const int GS = 148 * 4;  // grid-stride kernels

    // ---- build CSR for both matrices (replayed every launch) ----
    zero_counters<<<GS, T>>>();
    histogram<<<GS, T>>>(b_rows, cnt_b, nnz_b);
    histogram<<<GS, T>>>(i_rows, cnt_i, nnz_i);
    scan_rows<<<1, 1024>>>(cnt_b, rp_b, cur_b, N_BASKETS);
    scan_rows<<<1, 1024>>>(cnt_i, rp_i, cur_i, N_ITEMS);
    scatter_edges<<<GS, T>>>(b_rows, b_cols, b_vals, cur_b, edges_b, nnz_b);
    scatter_edges<<<GS, T>>>(i_rows, i_cols, i_vals, cur_i, edges_i, nnz_i);

    // ---- 3 layers of SpMM (no atomics, no zeroing) ----
    const int blocks_b = (N_BASKETS * 32 + T - 1) / T;
    const int blocks_i = (N_ITEMS * 32 + T - 1) / T;
    const size_t bstride = (size_t)N_BASKETS * DIM;
    const size_t istride = (size_t)N_ITEMS * DIM;

    const float* src = x;
    for (int layer = 0; layer < NUM_LAYER; layer++) {
        float* bdst = basket + (size_t)layer * bstride;
        float* idst = curbuf + (size_t)layer * istride;
        spmm_csr<<<blocks_b, T>>>(edges_b, rp_b, src, bdst, N_BASKETS);
        spmm_csr<<<blocks_i, T>>>(edges_i, rp_i, bdst, idst, N_ITEMS);
        src = idst;
    }

    // ---- finalize ----
    const int n_basket4 = N_BASKETS * DIM / 4;
    const int n_item4   = N_ITEMS * DIM / 4;
    const int n_tot4 = n_item4 + n_basket4;
    finalize<<<(n_tot4 + T - 1) / T, T>>>((const float4*)x, (float4*)out,
                                          n_item4, n_basket4);
}